// round 2
// baseline (speedup 1.0000x reference)
#include <cuda_runtime.h>
#include <math.h>

#define N 4096
#define NWORDS 128   // N/32

// ---------------- device scratch (no allocations allowed) ----------------
__device__ float    g_H[N * 512];
__device__ float    g_bufA[N * 512];
__device__ float    g_bufB[N * 512];
__device__ float    g_src[N];
__device__ float    g_tgt[N];
__device__ float    g_tmax[1];
__device__ unsigned g_adj[N * NWORDS];

// ---------------- adj int32 -> bitmask ----------------
__global__ void pack_adj(const int* __restrict__ adj) {
    int idx = blockIdx.x * blockDim.x + threadIdx.x;   // one thread per adj element
    unsigned b = __ballot_sync(0xffffffffu, adj[idx] > 0);
    if ((threadIdx.x & 31) == 0) g_adj[idx >> 5] = b;
}

// ---------------- tiled fp32 GEMM: C[M,Nn] = A[M,K] @ B[K,Nn] ----------------
template<int BM, int BN, int BK, int TM, int TN>
__global__ __launch_bounds__((BM/TM)*(BN/TN))
void sgemm(const float* __restrict__ A, const float* __restrict__ B,
           float* __restrict__ C, int M, int Nn, int K)
{
    constexpr int THREADS = (BM/TM)*(BN/TN);
    __shared__ float As[BK][BM + 1];
    __shared__ __align__(16) float Bs[BK][BN];
    int tid  = threadIdx.x;
    int row0 = blockIdx.y * BM, col0 = blockIdx.x * BN;
    int tx   = tid % (BN/TN), ty = tid / (BN/TN);
    float acc[TM][TN] = {};

    for (int k0 = 0; k0 < K; k0 += BK) {
        __syncthreads();
        for (int i = tid; i < BM*BK; i += THREADS) {
            int m = i / BK, k = i % BK;
            As[k][m] = A[(size_t)(row0 + m) * K + k0 + k];
        }
        for (int i = tid; i < BK*BN; i += THREADS) {
            int k = i / BN, n = i % BN;
            Bs[k][n] = B[(size_t)(k0 + k) * Nn + col0 + n];
        }
        __syncthreads();
        #pragma unroll 4
        for (int kk = 0; kk < BK; kk++) {
            float af[TM], bf[TN];
            #pragma unroll
            for (int m = 0; m < TM; m++) af[m] = As[kk][ty*TM + m];
            #pragma unroll
            for (int n = 0; n < TN; n++) bf[n] = Bs[kk][tx*TN + n];
            #pragma unroll
            for (int m = 0; m < TM; m++)
                #pragma unroll
                for (int n = 0; n < TN; n++) acc[m][n] += af[m] * bf[n];
        }
    }
    #pragma unroll
    for (int m = 0; m < TM; m++)
        #pragma unroll
        for (int n = 0; n < TN; n++)
            C[(size_t)(row0 + ty*TM + m) * Nn + col0 + tx*TN + n] = acc[m][n];
}

// ---------------- src/tgt: per-row dot of H with a[:fo], a[fo:] ----------------
__global__ void src_tgt(const float* __restrict__ H, const float* __restrict__ a, int fo)
{
    int row  = blockIdx.x * (blockDim.x / 32) + (threadIdx.x >> 5);
    int lane = threadIdx.x & 31;
    float s = 0.f, t = 0.f;
    for (int c = lane; c < fo; c += 32) {
        float h = H[(size_t)row * fo + c];
        s += h * a[c];
        t += h * a[fo + c];
    }
    #pragma unroll
    for (int o = 16; o; o >>= 1) {
        s += __shfl_xor_sync(0xffffffffu, s, o);
        t += __shfl_xor_sync(0xffffffffu, t, o);
    }
    if (!lane) { g_src[row] = s; g_tgt[row] = t; }
}

// ---------------- global max of tgt (single block) ----------------
__global__ void tmax_k()
{
    __shared__ float sm[1024];
    float m = -1e30f;
    for (int i = threadIdx.x; i < N; i += 1024) m = fmaxf(m, g_tgt[i]);
    sm[threadIdx.x] = m;
    __syncthreads();
    for (int s = 512; s; s >>= 1) {
        if (threadIdx.x < s) sm[threadIdx.x] = fmaxf(sm[threadIdx.x], sm[threadIdx.x + s]);
        __syncthreads();
    }
    if (!threadIdx.x) g_tmax[0] = sm[0];
}

// ---------------- fused masked-softmax attention GEMM ----------------
// OUT[i, :] = (1/Z_i) * sum_j adj_ij * exp(lrelu(src_i + tgt_j) - m_i) * H[j, :]
// BK must be 32 (one adj word per K-step).
template<int BM, int BN, int BK, int TM, int TN>
__global__ __launch_bounds__((BM/TM)*(BN/TN))
void attn(const float* __restrict__ H, float* __restrict__ OUT, int fo)
{
    constexpr int THREADS  = (BM/TM)*(BN/TN);
    constexpr int JJ_PER   = BM * BK / THREADS;
    constexpr int JSTRIDE  = THREADS / BM;
    static_assert(BK == 32, "BK must be 32");

    __shared__ __align__(16) float Ps[BK][BM + 4];
    __shared__ __align__(16) float Hs[BK][BN];
    __shared__ float tgt_s[BK];
    __shared__ float z_s[BM];

    int tid  = threadIdx.x;
    int row0 = blockIdx.y * BM, col0 = blockIdx.x * BN;
    int tx   = tid % (BN/TN), ty = tid / (BN/TN);

    float tmax = g_tmax[0];
    if (tid < BM) z_s[tid] = 0.f;

    // p-compute assignment: fixed row per thread -> Z accumulates in a register
    int   rp     = tid % BM;
    int   jj0    = tid / BM;
    float my_src = g_src[row0 + rp];
    float lm     = my_src + tmax;
    float my_m   = lm > 0.f ? lm : 0.2f * lm;
    const unsigned* adjrow = g_adj + (size_t)(row0 + rp) * NWORDS;
    float zloc = 0.f;

    float acc[TM][TN] = {};

    for (int k0 = 0; k0 < N; k0 += BK) {
        __syncthreads();                       // previous compute phase done
        if (tid < BK) tgt_s[tid] = g_tgt[k0 + tid];
        // load H tile (vectorized, coalesced)
        for (int i = tid; i < BK * BN / 4; i += THREADS) {
            int k = i / (BN/4), v = i % (BN/4);
            float4 t = reinterpret_cast<const float4*>(H + (size_t)(k0 + k) * fo + col0)[v];
            reinterpret_cast<float4*>(&Hs[k][0])[v] = t;
        }
        __syncthreads();                       // tgt_s / Hs ready
        // compute P tile
        unsigned aw = adjrow[k0 >> 5];
        #pragma unroll
        for (int s = 0; s < JJ_PER; s++) {
            int jj = jj0 + s * JSTRIDE;
            float l = my_src + tgt_s[jj];
            l = l > 0.f ? l : 0.2f * l;
            float p = __expf(l - my_m);
            p = ((aw >> jj) & 1u) ? p : 0.f;
            Ps[jj][rp] = p;
            zloc += p;
        }
        __syncthreads();                       // Ps ready
        #pragma unroll 4
        for (int kk = 0; kk < BK; kk++) {
            float pf[TM], hf[TN];
            #pragma unroll
            for (int m = 0; m < TM; m++) pf[m] = Ps[kk][ty*TM + m];
            #pragma unroll
            for (int n = 0; n < TN; n++) hf[n] = Hs[kk][tx*TN + n];
            #pragma unroll
            for (int m = 0; m < TM; m++)
                #pragma unroll
                for (int n = 0; n < TN; n++) acc[m][n] += pf[m] * hf[n];
        }
    }

    atomicAdd(&z_s[rp], zloc);
    __syncthreads();
    #pragma unroll
    for (int m = 0; m < TM; m++) {
        float invz = 1.f / z_s[ty*TM + m];
        #pragma unroll
        for (int n = 0; n < TN; n++)
            OUT[(size_t)(row0 + ty*TM + m) * fo + col0 + tx*TN + n] = acc[m][n] * invz;
    }
}

// ---------------- orchestration ----------------
extern "C" void kernel_launch(void* const* d_in, const int* in_sizes, int n_in,
                              void* d_out, int out_size)
{
    const float* x   = (const float*)d_in[0];
    const int*   adj = (const int*)d_in[1];
    const float* w[8]; const float* a[8];
    for (int i = 0; i < 8; i++) {
        w[i] = (const float*)d_in[2 + 2*i];
        a[i] = (const float*)d_in[3 + 2*i];
    }
    float* out = (float*)d_out;

    float *H, *bufA, *bufB;
    cudaGetSymbolAddress((void**)&H,    g_H);
    cudaGetSymbolAddress((void**)&bufA, g_bufA);
    cudaGetSymbolAddress((void**)&bufB, g_bufB);

    // output layout: (x_bar[4096,512], h1[4096,256], h2[4096,128], h3[4096,64], h4[4096,16])
    const size_t OFF_H1 = (size_t)N * 512;
    const size_t OFF_H2 = OFF_H1 + (size_t)N * 256;
    const size_t OFF_H3 = OFF_H2 + (size_t)N * 128;
    const size_t OFF_H4 = OFF_H3 + (size_t)N * 64;

    pack_adj<<<(size_t)N * N / 256, 256>>>(adj);

    const int FI[8] = {512, 256, 128, 64, 16,  64, 128, 256};
    const int FO[8] = {256, 128,  64, 16, 64, 128, 256, 512};
    float* outs[8] = { out + OFF_H1, out + OFF_H2, out + OFF_H3, out + OFF_H4,
                       bufA, bufB, bufA, out };
    const float* ins[8];
    ins[0] = x;
    for (int l = 1; l < 8; l++) ins[l] = outs[l - 1];

    for (int l = 0; l < 8; l++) {
        int fi = FI[l], fo = FO[l];

        // H = X @ W
        if (fo >= 64)
            sgemm<64, 64, 16, 4, 4><<<dim3(fo / 64, N / 64), 256>>>(ins[l], w[l], H, N, fo, fi);
        else
            sgemm<64, 16, 16, 4, 1><<<dim3(1, N / 64), 256>>>(ins[l], w[l], H, N, fo, fi);

        src_tgt<<<N / 8, 256>>>(H, a[l], fo);
        tmax_k<<<1, 1024>>>();

        switch (fo) {
            case 512: attn<128, 128, 32, 8, 8><<<dim3(4, N / 128), 256>>>(H, outs[l], fo); break;
            case 256: attn< 64, 128, 32, 4, 8><<<dim3(2, N /  64), 256>>>(H, outs[l], fo); break;
            case 128: attn< 32, 128, 32, 2, 8><<<dim3(1, N /  32), 256>>>(H, outs[l], fo); break;
            case  64: attn< 32,  64, 32, 2, 4><<<dim3(1, N /  32), 256>>>(H, outs[l], fo); break;
            case  16: attn< 32,  16, 32, 2, 1><<<dim3(1, N /  32), 256>>>(H, outs[l], fo); break;
        }
    }
    (void)in_sizes; (void)n_in; (void)out_size;
}

// round 6
// speedup vs baseline: 2.9220x; 2.9220x over previous
#include <cuda_runtime.h>
#include <cuda_bf16.h>
#include <stdint.h>
#include <math.h>

#define N 4096
#define NWORDS 128   // N/32
#define LOG2E 1.44269504088896f

// ---------------- device scratch ----------------
__device__ float    g_H[N * 512];
__device__ float    g_bufA[N * 512];
__device__ float    g_bufB[N * 512];
__device__ float    g_src[N];
__device__ float    g_tgt[N];
__device__ float    g_tmax[1];
__device__ unsigned g_adj[N * NWORDS];

// ---------------- helpers ----------------
__device__ __forceinline__ uint32_t smem_u32(const void* p) {
    uint32_t a;
    asm("{ .reg .u64 t; cvta.to.shared.u64 t, %1; cvt.u32.u64 %0, t; }" : "=r"(a) : "l"(p));
    return a;
}
__device__ __forceinline__ float ex2f(float x) {
    float y; asm("ex2.approx.ftz.f32 %0, %1;" : "=f"(y) : "f"(x)); return y;
}
__device__ __forceinline__ uint32_t packbf(float a, float b) {
    __nv_bfloat162 h = __floats2bfloat162_rn(a, b);
    return *(uint32_t*)&h;
}
__device__ __forceinline__ void ldsm4t(uint32_t& r0, uint32_t& r1, uint32_t& r2, uint32_t& r3,
                                       uint32_t addr) {
    asm volatile("ldmatrix.sync.aligned.m8n8.x4.trans.shared.b16 {%0,%1,%2,%3}, [%4];"
                 : "=r"(r0), "=r"(r1), "=r"(r2), "=r"(r3) : "r"(addr));
}
__device__ __forceinline__ void mma16816(float* c, uint32_t a0, uint32_t a1, uint32_t a2,
                                         uint32_t a3, uint32_t b0, uint32_t b1) {
    asm volatile("mma.sync.aligned.m16n8k16.row.col.f32.bf16.bf16.f32 "
                 "{%0,%1,%2,%3}, {%4,%5,%6,%7}, {%8,%9}, {%0,%1,%2,%3};"
                 : "+f"(c[0]), "+f"(c[1]), "+f"(c[2]), "+f"(c[3])
                 : "r"(a0), "r"(a1), "r"(a2), "r"(a3), "r"(b0), "r"(b1));
}
// p = adj ? exp2(lrelu(src+t)*log2e - mscaled) : 0
__device__ __forceinline__ float pv(float src, float mscaled, float t, unsigned aw, int sh) {
    float l = src + t;
    l = fmaxf(l, 0.2f * l);
    float arg = fmaf(l, LOG2E, -mscaled);
    arg = ((aw >> sh) & 1u) ? arg : -1e30f;
    return ex2f(arg);
}

// ---------------- adj int32 -> bitmask ----------------
__global__ void pack_adj(const int* __restrict__ adj) {
    int idx = blockIdx.x * blockDim.x + threadIdx.x;
    unsigned b = __ballot_sync(0xffffffffu, adj[idx] > 0);
    if ((threadIdx.x & 31) == 0) g_adj[idx >> 5] = b;
}

// ---------------- tiled fp32 GEMM (features) ----------------
template<int BM, int BN, int BK, int TM, int TN>
__global__ __launch_bounds__((BM/TM)*(BN/TN))
void sgemm(const float* __restrict__ A, const float* __restrict__ B,
           float* __restrict__ C, int M, int Nn, int K)
{
    constexpr int THREADS = (BM/TM)*(BN/TN);
    __shared__ float As[BK][BM + 1];
    __shared__ __align__(16) float Bs[BK][BN];
    int tid  = threadIdx.x;
    int row0 = blockIdx.y * BM, col0 = blockIdx.x * BN;
    int tx   = tid % (BN/TN), ty = tid / (BN/TN);
    float acc[TM][TN] = {};
    for (int k0 = 0; k0 < K; k0 += BK) {
        __syncthreads();
        for (int i = tid; i < BM*BK; i += THREADS) {
            int m = i / BK, k = i % BK;
            As[k][m] = A[(size_t)(row0 + m) * K + k0 + k];
        }
        for (int i = tid; i < BK*BN; i += THREADS) {
            int k = i / BN, n = i % BN;
            Bs[k][n] = B[(size_t)(k0 + k) * Nn + col0 + n];
        }
        __syncthreads();
        #pragma unroll 4
        for (int kk = 0; kk < BK; kk++) {
            float af[TM], bf[TN];
            #pragma unroll
            for (int m = 0; m < TM; m++) af[m] = As[kk][ty*TM + m];
            #pragma unroll
            for (int n = 0; n < TN; n++) bf[n] = Bs[kk][tx*TN + n];
            #pragma unroll
            for (int m = 0; m < TM; m++)
                #pragma unroll
                for (int n = 0; n < TN; n++) acc[m][n] += af[m] * bf[n];
        }
    }
    #pragma unroll
    for (int m = 0; m < TM; m++)
        #pragma unroll
        for (int n = 0; n < TN; n++)
            C[(size_t)(row0 + ty*TM + m) * Nn + col0 + tx*TN + n] = acc[m][n];
}

// ---------------- src/tgt ----------------
__global__ void src_tgt(const float* __restrict__ H, const float* __restrict__ a, int fo)
{
    int row  = blockIdx.x * (blockDim.x / 32) + (threadIdx.x >> 5);
    int lane = threadIdx.x & 31;
    float s = 0.f, t = 0.f;
    for (int c = lane; c < fo; c += 32) {
        float h = H[(size_t)row * fo + c];
        s += h * a[c];
        t += h * a[fo + c];
    }
    #pragma unroll
    for (int o = 16; o; o >>= 1) {
        s += __shfl_xor_sync(0xffffffffu, s, o);
        t += __shfl_xor_sync(0xffffffffu, t, o);
    }
    if (!lane) { g_src[row] = s; g_tgt[row] = t; }
}

__global__ void tmax_k()
{
    __shared__ float sm[1024];
    float m = -1e30f;
    for (int i = threadIdx.x; i < N; i += 1024) m = fmaxf(m, g_tgt[i]);
    sm[threadIdx.x] = m;
    __syncthreads();
    for (int s = 512; s; s >>= 1) {
        if (threadIdx.x < s) sm[threadIdx.x] = fmaxf(sm[threadIdx.x], sm[threadIdx.x + s]);
        __syncthreads();
    }
    if (!threadIdx.x) g_tmax[0] = sm[0];
}

// ---------------- HMMA fused attention ----------------
// CTA: ROWS=16*RW rows, NMMA-col section. 8 warps in (RW x CW) grid, warp tile 16 x (NMMA/CW).
// K loop: 64 stages of 64. P fragments computed in registers (A-frag layout),
// H split bf16 hi/lo in padded smem, B-frags via ldmatrix.x4.trans.
// 3 streams: Phi*Hhi + Phi*Hlo + Plo*Hhi.
template<int NMMA, int RW, int CW>
__global__ __launch_bounds__(256)
void attn_mma(const float* __restrict__ H, float* __restrict__ OUT, int fo)
{
    constexpr int ROWS = 16 * RW;
    constexpr int NW   = NMMA / CW;
    constexpr int NCP  = (NW + 15) / 16;     // ldmatrix chunk-pairs per warp
    constexpr int LDH  = NMMA + 8;           // pad: row stride % 128B == 16/48 -> conflict-free
    constexpr int V    = NMMA / 4;

    __shared__ __align__(16) __nv_bfloat16 HsHi[64][LDH];
    __shared__ __align__(16) __nv_bfloat16 HsLo[64][LDH];
    __shared__ float tgt_s[64];

    int tid = threadIdx.x, lane = tid & 31, wid = tid >> 5;
    int warpR = wid / CW, warpC = wid % CW;
    int row0 = blockIdx.y * ROWS;
    int col0 = blockIdx.x * NMMA;
    int q = lane & 3;

    float tmax = g_tmax[0];
    int r0 = row0 + warpR * 16 + (lane >> 2);
    int r1 = r0 + 8;
    float s0 = g_src[r0], s1 = g_src[r1];
    float lm0 = s0 + tmax, lm1 = s1 + tmax;
    float m0 = fmaxf(lm0, 0.2f * lm0) * LOG2E;
    float m1 = fmaxf(lm1, 0.2f * lm1) * LOG2E;
    const unsigned* a0p = g_adj + (size_t)r0 * NWORDS;
    const unsigned* a1p = g_adj + (size_t)r1 * NWORDS;
    float z0 = 0.f, z1 = 0.f;

    float acc[NCP][8] = {};

    uint32_t lrow = lane & 15, lc8 = (lane >> 4) * 8;
    uint32_t bHi = smem_u32(&HsHi[lrow][warpC * NW + lc8]);
    uint32_t bLo = smem_u32(&HsLo[lrow][warpC * NW + lc8]);

    for (int st = 0; st < 64; st++) {
        // prefetch adj words for this stage (latency hidden by H load/convert)
        unsigned w00 = a0p[st * 2], w01 = a0p[st * 2 + 1];
        unsigned w10 = a1p[st * 2], w11 = a1p[st * 2 + 1];

        __syncthreads();   // previous stage's MMAs done reading smem
        #pragma unroll
        for (int idx = tid; idx < 64 * V; idx += 256) {
            int k = idx / V, v = idx % V;
            float4 h = *(const float4*)(H + (size_t)(st * 64 + k) * fo + col0 + 4 * v);
            __nv_bfloat162 h01 = __floats2bfloat162_rn(h.x, h.y);
            __nv_bfloat162 h23 = __floats2bfloat162_rn(h.z, h.w);
            __nv_bfloat162 l01 = __floats2bfloat162_rn(h.x - __bfloat162float(h01.x),
                                                       h.y - __bfloat162float(h01.y));
            __nv_bfloat162 l23 = __floats2bfloat162_rn(h.z - __bfloat162float(h23.x),
                                                       h.w - __bfloat162float(h23.y));
            uint2 hw, lw;
            hw.x = *(uint32_t*)&h01; hw.y = *(uint32_t*)&h23;
            lw.x = *(uint32_t*)&l01; lw.y = *(uint32_t*)&l23;
            *(uint2*)&HsHi[k][4 * v] = hw;
            *(uint2*)&HsLo[k][4 * v] = lw;
        }
        if (tid < 64) tgt_s[tid] = g_tgt[st * 64 + tid];
        __syncthreads();

        #pragma unroll
        for (int ks = 0; ks < 4; ks++) {
            unsigned aw0 = (ks < 2) ? w00 : w01;
            unsigned aw1 = (ks < 2) ? w10 : w11;
            int sh = ((ks & 1) << 4) + 2 * q;
            int kl = ks * 16 + 2 * q;
            float t0 = tgt_s[kl],     t1 = tgt_s[kl + 1];
            float t8 = tgt_s[kl + 8], t9 = tgt_s[kl + 9];

            float p00 = pv(s0, m0, t0, aw0, sh),     p01 = pv(s0, m0, t1, aw0, sh + 1);
            float p08 = pv(s0, m0, t8, aw0, sh + 8), p09 = pv(s0, m0, t9, aw0, sh + 9);
            float p10 = pv(s1, m1, t0, aw1, sh),     p11 = pv(s1, m1, t1, aw1, sh + 1);
            float p18 = pv(s1, m1, t8, aw1, sh + 8), p19 = pv(s1, m1, t9, aw1, sh + 9);
            z0 += (p00 + p01) + (p08 + p09);
            z1 += (p10 + p11) + (p18 + p19);

            uint32_t ah0 = packbf(p00, p01), ah1 = packbf(p10, p11);
            uint32_t ah2 = packbf(p08, p09), ah3 = packbf(p18, p19);
            __nv_bfloat162 v0 = *(__nv_bfloat162*)&ah0, v1 = *(__nv_bfloat162*)&ah1;
            __nv_bfloat162 v2 = *(__nv_bfloat162*)&ah2, v3 = *(__nv_bfloat162*)&ah3;
            uint32_t al0 = packbf(p00 - __bfloat162float(v0.x), p01 - __bfloat162float(v0.y));
            uint32_t al1 = packbf(p10 - __bfloat162float(v1.x), p11 - __bfloat162float(v1.y));
            uint32_t al2 = packbf(p08 - __bfloat162float(v2.x), p09 - __bfloat162float(v2.y));
            uint32_t al3 = packbf(p18 - __bfloat162float(v3.x), p19 - __bfloat162float(v3.y));

            uint32_t rowoff = (uint32_t)(ks * 16 * LDH * 2);
            #pragma unroll
            for (int cp = 0; cp < NCP; cp++) {
                uint32_t off = rowoff + (uint32_t)(cp * 32);
                uint32_t h0, h1, h2, h3, L0, L1, L2, L3;
                ldsm4t(h0, h1, h2, h3, bHi + off);
                ldsm4t(L0, L1, L2, L3, bLo + off);
                mma16816(acc[cp],     ah0, ah1, ah2, ah3, h0, h1);
                mma16816(acc[cp],     ah0, ah1, ah2, ah3, L0, L1);
                mma16816(acc[cp],     al0, al1, al2, al3, h0, h1);
                mma16816(acc[cp] + 4, ah0, ah1, ah2, ah3, h2, h3);
                mma16816(acc[cp] + 4, ah0, ah1, ah2, ah3, L2, L3);
                mma16816(acc[cp] + 4, al0, al1, al2, al3, h2, h3);
            }
        }
    }

    // Z reduce within quad (lanes sharing the same rows)
    z0 += __shfl_xor_sync(0xffffffffu, z0, 1);
    z0 += __shfl_xor_sync(0xffffffffu, z0, 2);
    z1 += __shfl_xor_sync(0xffffffffu, z1, 1);
    z1 += __shfl_xor_sync(0xffffffffu, z1, 2);
    float iz0 = 1.f / z0, iz1 = 1.f / z1;

    #pragma unroll
    for (int cp = 0; cp < NCP; cp++) {
        #pragma unroll
        for (int c = 0; c < 2; c++) {
            if (cp * 16 + c * 8 < NW) {
                int ncol = col0 + warpC * NW + cp * 16 + c * 8 + 2 * q;
                float2 o0, o1;
                o0.x = acc[cp][c * 4 + 0] * iz0; o0.y = acc[cp][c * 4 + 1] * iz0;
                o1.x = acc[cp][c * 4 + 2] * iz1; o1.y = acc[cp][c * 4 + 3] * iz1;
                *(float2*)(OUT + (size_t)r0 * fo + ncol) = o0;
                *(float2*)(OUT + (size_t)r1 * fo + ncol) = o1;
            }
        }
    }
}

// ---------------- orchestration ----------------
extern "C" void kernel_launch(void* const* d_in, const int* in_sizes, int n_in,
                              void* d_out, int out_size)
{
    const float* x   = (const float*)d_in[0];
    const int*   adj = (const int*)d_in[1];
    const float* w[8]; const float* a[8];
    for (int i = 0; i < 8; i++) {
        w[i] = (const float*)d_in[2 + 2*i];
        a[i] = (const float*)d_in[3 + 2*i];
    }
    float* out = (float*)d_out;

    float *H, *bufA, *bufB;
    cudaGetSymbolAddress((void**)&H,    g_H);
    cudaGetSymbolAddress((void**)&bufA, g_bufA);
    cudaGetSymbolAddress((void**)&bufB, g_bufB);

    const size_t OFF_H1 = (size_t)N * 512;
    const size_t OFF_H2 = OFF_H1 + (size_t)N * 256;
    const size_t OFF_H3 = OFF_H2 + (size_t)N * 128;
    const size_t OFF_H4 = OFF_H3 + (size_t)N * 64;

    pack_adj<<<(size_t)N * N / 256, 256>>>(adj);

    const int FI[8] = {512, 256, 128, 64, 16,  64, 128, 256};
    const int FO[8] = {256, 128,  64, 16, 64, 128, 256, 512};
    float* outs[8] = { out + OFF_H1, out + OFF_H2, out + OFF_H3, out + OFF_H4,
                       bufA, bufB, bufA, out };
    const float* ins[8];
    ins[0] = x;
    for (int l = 1; l < 8; l++) ins[l] = outs[l - 1];

    for (int l = 0; l < 8; l++) {
        int fi = FI[l], fo = FO[l];

        if (fo >= 64)
            sgemm<64, 64, 16, 4, 4><<<dim3(fo / 64, N / 64), 256>>>(ins[l], w[l], H, N, fo, fi);
        else
            sgemm<64, 16, 16, 4, 1><<<dim3(1, N / 64), 256>>>(ins[l], w[l], H, N, fo, fi);

        src_tgt<<<N / 8, 256>>>(H, a[l], fo);
        tmax_k<<<1, 1024>>>();

        switch (fo) {
            case 512:  // NMMA=128, 4 sections, ROWS=128 (RW=8, CW=1)
                attn_mma<128, 8, 1><<<dim3(4, N / 128), 256>>>(H, outs[l], fo); break;
            case 256:  // NMMA=128, 2 sections, ROWS=64 (RW=4, CW=2)
                attn_mma<128, 4, 2><<<dim3(2, N / 64), 256>>>(H, outs[l], fo); break;
            case 128:  // NMMA=128, 1 section, ROWS=32 (RW=2, CW=4)
                attn_mma<128, 2, 4><<<dim3(1, N / 32), 256>>>(H, outs[l], fo); break;
            case 64:   // NMMA=64, 1 section, ROWS=32 (RW=2, CW=4)
                attn_mma<64, 2, 4><<<dim3(1, N / 32), 256>>>(H, outs[l], fo); break;
            case 16:   // NMMA=16, 1 section, ROWS=64 (RW=4, CW=2)
                attn_mma<16, 4, 2><<<dim3(1, N / 64), 256>>>(H, outs[l], fo); break;
        }
    }
    (void)in_sizes; (void)n_in; (void)out_size;
}